// round 9
// baseline (speedup 1.0000x reference)
#include <cuda_runtime.h>
#include <cuda_bf16.h>
#include <math.h>
#include <stdint.h>

#define C_CH   128
#define N_PTS  32768
#define K_PWL  20
#define LATENT 8
#define HID    8
#define NSEG   (K_PWL - 1)

// ---------------- scratch (static device memory; no allocations) ----------------
__device__ float g_x[(size_t)C_CH * N_PTS];     // raw x MLP outputs [C][N]
__device__ float g_e[(size_t)C_CH * N_PTS];     // raw e MLP outputs [C][N]
__device__ float g_slope[C_CH * NSEG];          // per-channel PWL segment slopes
__device__ float g_icept[C_CH * NSEG];          // per-channel PWL segment intercepts
__device__ unsigned int g_minbits[C_CH];
__device__ unsigned int g_maxbits[C_CH];
__device__ float g_minv[C_CH];
__device__ float g_scale[C_CH];
__device__ float g_psum[2048];
__device__ float g_psumsq[2048];
__device__ float g_eA;   // 0.1 * invstd
__device__ float g_eB;   // -0.1 * mean * invstd
__device__ unsigned int g_done;  // static zero-init; reset by finalize each run

// xp = linspace(0,1,20) in f32
#define XPV(k) ((float)((double)(k) / 19.0))
__constant__ float c_xp[K_PWL] = {
    XPV(0), XPV(1), XPV(2), XPV(3), XPV(4), XPV(5), XPV(6), XPV(7), XPV(8), XPV(9),
    XPV(10), XPV(11), XPV(12), XPV(13), XPV(14), XPV(15), XPV(16), XPV(17), XPV(18), XPV(19)
};

// ---------------- helpers ----------------
__device__ __forceinline__ unsigned int fenc(float f) {
    unsigned int u = __float_as_uint(f);
    return (u >> 31) ? ~u : (u | 0x80000000u);
}
__device__ __forceinline__ float fdec(unsigned int u) {
    return (u & 0x80000000u) ? __uint_as_float(u & 0x7FFFFFFFu) : __uint_as_float(~u);
}

// Fast, tight-absolute-error tanh: (e^{2x}-1)/(e^{2x}+1). abs err ~1e-7.
__device__ __forceinline__ float tanh_fast(float x) {
    x = fminf(fmaxf(x, -30.0f), 30.0f);
    float t = __expf(2.0f * x);
    return __fdividef(t - 1.0f, t + 1.0f);
}

// ---------------- gen path: PWL generator + slope/intercept tables ----------------
// Runs as the LAST block of pass_x (threads 0..127 active).
__device__ void gen_pwl_block(const float* __restrict__ zf,
                              const float* __restrict__ Wf1, const float* __restrict__ bf1,
                              const float* __restrict__ Wf2, const float* __restrict__ bf2,
                              const void* __restrict__ dirs_raw,
                              unsigned int* flags_sh) {
    const int c = threadIdx.x;
    if (c >= C_CH) return;
    // Parallel dtype detection for `directions`:
    //   bit0 -> some byte at offset %4 != 0 is nonzero  (NOT int32 0/1)
    //   bit1 -> some byte value > 1                     (NOT a 0/1 byte array)
    if (c == 0) *flags_sh = 0u;
    __syncwarp();
    __syncthreads();
    {
        unsigned char v = ((const unsigned char*)dirs_raw)[c];
        unsigned int f = 0u;
        if ((c & 3) != 0 && v != 0) f |= 1u;
        if (v > 1) f |= 2u;
        if (f) atomicOr(flags_sh, f);
    }
    __syncthreads();
    const unsigned int flags = *flags_sh;
    // mode: 0 = int32, 1 = uint8/bool, 2 = float32
    const int mode = (!(flags & 1u)) ? 0 : ((!(flags & 2u)) ? 1 : 2);

    float z[LATENT];
#pragma unroll
    for (int i = 0; i < LATENT; i++) z[i] = zf[c * LATENT + i];

    float h[HID];
#pragma unroll
    for (int j = 0; j < HID; j++) h[j] = bf1[j];
#pragma unroll
    for (int i = 0; i < LATENT; i++)
#pragma unroll
        for (int j = 0; j < HID; j++) h[j] = fmaf(z[i], Wf1[i * HID + j], h[j]);
#pragma unroll
    for (int j = 0; j < HID; j++) h[j] = tanh_fast(h[j]);

    float pts[K_PWL];
#pragma unroll
    for (int k = 0; k < K_PWL; k++) {
        float s = bf2[k];
#pragma unroll
        for (int j = 0; j < HID; j++) s = fmaf(h[j], Wf2[j * K_PWL + k], s);
        pts[k] = tanh_fast(s);
    }
    // insertion sort ascending
    for (int a = 1; a < K_PWL; a++) {
        float v = pts[a];
        int b = a - 1;
        while (b >= 0 && pts[b] > v) { pts[b + 1] = pts[b]; b--; }
        pts[b + 1] = v;
    }
    bool dir;
    if (mode == 0)      dir = ((const int*)dirs_raw)[c] != 0;
    else if (mode == 1) dir = ((const unsigned char*)dirs_raw)[c] != 0;
    else                dir = ((const float*)dirs_raw)[c] > 0.5f;

    // Per-segment slope/intercept: y(xv) = sl*xv + ic on [xp[k], xp[k+1]]
    for (int k = 0; k < NSEG; k++) {
        float y0 = dir ? pts[k]     : pts[K_PWL - 1 - k];
        float y1 = dir ? pts[k + 1] : pts[K_PWL - 2 - k];
        float sl = (y1 - y0) / (c_xp[k + 1] - c_xp[k] + 1e-7f);
        g_slope[c * NSEG + k] = sl;
        g_icept[c * NSEG + k] = fmaf(-c_xp[k], sl, y0);
    }
}

// ---------------- K1: x MLP + per-channel min/max (+ gen block) ----------------
// 1D grid of 2049 blocks: blocks 0..2047 = MLP tiles (c = bid>>4, nchunk = bid&15);
// block 2048 = PWL generator.
__global__ void __launch_bounds__(256) pass_x_kernel(
    const float* __restrict__ zx,
    const float* __restrict__ W1, const float* __restrict__ b1,
    const float* __restrict__ W2, const float* __restrict__ b2,
    const float* __restrict__ zf,
    const float* __restrict__ Wf1, const float* __restrict__ bf1,
    const float* __restrict__ Wf2, const float* __restrict__ bf2,
    const void* __restrict__ dirs_raw) {
    __shared__ float red[256];
    const int bid = blockIdx.x;
    if (bid == 2048) {
        gen_pwl_block(zf, Wf1, bf1, Wf2, bf2, dirs_raw, (unsigned int*)red);
        return;
    }

    float W1r[64];
#pragma unroll
    for (int i = 0; i < 64; i++) W1r[i] = __ldg(W1 + i);
    float b1r[HID], W2r[HID];
#pragma unroll
    for (int j = 0; j < HID; j++) { b1r[j] = __ldg(b1 + j); W2r[j] = __ldg(W2 + j); }
    float b2r = __ldg(b2);

    const int c = bid >> 4;
    const int tid = threadIdx.x;
    const size_t base = (size_t)c * N_PTS;
    const int n0 = (bid & 15) * 2048;

    float lmin = 1e30f, lmax = -1e30f;
#pragma unroll
    for (int k = 0; k < 8; k++) {
        int n = n0 + k * 256 + tid;
        const float4* p = reinterpret_cast<const float4*>(zx + (base + n) * LATENT);
        float4 a = __ldcs(p);          // streaming read: don't evict scratch from L2
        float4 bq = __ldcs(p + 1);
        float z[8] = {a.x, a.y, a.z, a.w, bq.x, bq.y, bq.z, bq.w};
        float h[HID];
#pragma unroll
        for (int j = 0; j < HID; j++) h[j] = b1r[j];
#pragma unroll
        for (int i = 0; i < LATENT; i++)
#pragma unroll
            for (int j = 0; j < HID; j++) h[j] = fmaf(z[i], W1r[i * HID + j], h[j]);
        float o = b2r;
#pragma unroll
        for (int j = 0; j < HID; j++) o = fmaf(tanh_fast(h[j]), W2r[j], o);
        float xv = tanh_fast(o);
        g_x[base + n] = xv;            // default policy: keep in L2 for out_kernel
        lmin = fminf(lmin, xv);
        lmax = fmaxf(lmax, xv);
    }

    red[tid] = lmin; __syncthreads();
    for (int s = 128; s; s >>= 1) { if (tid < s) red[tid] = fminf(red[tid], red[tid + s]); __syncthreads(); }
    if (tid == 0) atomicMin(&g_minbits[c], fenc(red[0]));
    __syncthreads();
    red[tid] = lmax; __syncthreads();
    for (int s = 128; s; s >>= 1) { if (tid < s) red[tid] = fmaxf(red[tid], red[tid + s]); __syncthreads(); }
    if (tid == 0) atomicMax(&g_maxbits[c], fenc(red[0]));
}

// ---------------- K2: e MLP + global sum/sumsq partials + last-block finalize ----------------
__global__ void __launch_bounds__(256) pass_e_kernel(
    const float* __restrict__ ze,
    const float* __restrict__ W1, const float* __restrict__ b1,
    const float* __restrict__ W2, const float* __restrict__ b2) {
    float W1r[64];
#pragma unroll
    for (int i = 0; i < 64; i++) W1r[i] = __ldg(W1 + i);
    float b1r[HID], W2r[HID];
#pragma unroll
    for (int j = 0; j < HID; j++) { b1r[j] = __ldg(b1 + j); W2r[j] = __ldg(W2 + j); }
    float b2r = __ldg(b2);

    const int c = blockIdx.y;
    const int tid = threadIdx.x;
    const size_t base = (size_t)c * N_PTS;
    const int n0 = blockIdx.x * 2048;

    float ls = 0.0f, lq = 0.0f;
#pragma unroll
    for (int k = 0; k < 8; k++) {
        int n = n0 + k * 256 + tid;
        const float4* p = reinterpret_cast<const float4*>(ze + (base + n) * LATENT);
        float4 a = __ldcs(p);          // streaming read: protect g_x/g_e in L2
        float4 bq = __ldcs(p + 1);
        float z[8] = {a.x, a.y, a.z, a.w, bq.x, bq.y, bq.z, bq.w};
        float h[HID];
#pragma unroll
        for (int j = 0; j < HID; j++) h[j] = b1r[j];
#pragma unroll
        for (int i = 0; i < LATENT; i++)
#pragma unroll
            for (int j = 0; j < HID; j++) h[j] = fmaf(z[i], W1r[i * HID + j], h[j]);
        float o = b2r;
#pragma unroll
        for (int j = 0; j < HID; j++) o = fmaf(tanh_fast(h[j]), W2r[j], o);
        float ev = tanh_fast(o);
        g_e[base + n] = ev;
        ls += ev;
        lq = fmaf(ev, ev, lq);
    }

    __shared__ float reds[256];
    __shared__ float redq[256];
    __shared__ bool amLast;
    reds[tid] = ls; redq[tid] = lq; __syncthreads();
    for (int s = 128; s; s >>= 1) {
        if (tid < s) { reds[tid] += reds[tid + s]; redq[tid] += redq[tid + s]; }
        __syncthreads();
    }
    if (tid == 0) {
        int pid = blockIdx.y * gridDim.x + blockIdx.x;
        g_psum[pid] = reds[0];
        g_psumsq[pid] = redq[0];
        __threadfence();                       // release partials
        unsigned int t = atomicAdd(&g_done, 1u);
        amLast = (t == 2048u - 1u);
    }
    __syncthreads();

    // Last block performs the deterministic fixed-order fp64 reduce.
    if (amLast) {
        __threadfence();                       // acquire all partials
        __shared__ double sds[256];
        __shared__ double sdq[256];
        double s = 0.0, q = 0.0;
#pragma unroll
        for (int i = 0; i < 8; i++) {
            int idx = tid + i * 256;
            s += (double)g_psum[idx];
            q += (double)g_psumsq[idx];
        }
        sds[tid] = s; sdq[tid] = q; __syncthreads();
        for (int k = 128; k; k >>= 1) {
            if (tid < k) { sds[tid] += sds[tid + k]; sdq[tid] += sdq[tid + k]; }
            __syncthreads();
        }
        if (tid == 0) {
            double CN = (double)C_CH * (double)N_PTS;
            double mean = sds[0] / CN;
            double var = (sdq[0] - sds[0] * sds[0] / CN) / (CN - 1.0);
            double invstd = 1.0 / sqrt(var);
            g_eA = (float)(0.1 * invstd);
            g_eB = (float)(-0.1 * mean * invstd);
            g_done = 0u;                       // reset for next graph replay
        }
        if (tid < C_CH) {
            float mn = fdec(g_minbits[tid]);   // pass_x completed before this kernel (stream order)
            float mx = fdec(g_maxbits[tid]);
            g_minv[tid] = mn;
            g_scale[tid] = 1.0f / (mx - mn);
        }
        __threadfence();
    }
}

// ---------------- K3: transpose + direct-index PWL + noise ----------------
// Block covers 32 channels x 128 n (4 sub-tiles of 32x32).
__global__ void __launch_bounds__(256, 8) out_kernel(float* __restrict__ out) {
    __shared__ float sx[32][33];
    __shared__ float se[32][33];
    __shared__ float ssl[32][NSEG + 1];
    __shared__ float ssb[32][NSEG + 1];
    __shared__ float smn[32];
    __shared__ float ssc[32];

    const int tx = threadIdx.x, ty = threadIdx.y;
    const int tid = ty * 32 + tx;
    const int nb = blockIdx.x * 128;
    const int c0 = blockIdx.y * 32;

    for (int idx = tid; idx < 32 * NSEG; idx += 256) {
        int cl = idx / NSEG, k = idx % NSEG;
        ssl[cl][k] = g_slope[(c0 + cl) * NSEG + k];
        ssb[cl][k] = g_icept[(c0 + cl) * NSEG + k];
    }
    if (tid < 32) {
        smn[tid] = g_minv[c0 + tid];
        ssc[tid] = g_scale[c0 + tid];
    }
    const float eA = g_eA, eB = g_eB;
    __syncthreads();

    const float mn = smn[tx], sc = ssc[tx];

#pragma unroll
    for (int t = 0; t < 4; t++) {
        const int n0 = nb + t * 32;
#pragma unroll
        for (int r = 0; r < 4; r++) {
            int cl = ty + r * 8;
            size_t off = (size_t)(c0 + cl) * N_PTS + n0 + tx;
            sx[cl][tx] = __ldcs(&g_x[off]);   // read-once: evict-first
            se[cl][tx] = __ldcs(&g_e[off]);
        }
        __syncthreads();
#pragma unroll
        for (int r = 0; r < 4; r++) {
            int nn = ty + r * 8;
            float xv = (sx[tx][nn] - mn) * sc;
            int j = min(max(__float2int_rd(xv * 19.0f), 0), NSEG - 1);
            float y = fmaf(xv, ssl[tx][j], ssb[tx][j]);
            __stcs(&out[(size_t)(n0 + nn) * C_CH + c0 + tx], fmaf(se[tx][nn], eA, y + eB));
        }
        __syncthreads();
    }
}

// ---------------- launch ----------------
extern "C" void kernel_launch(void* const* d_in, const int* in_sizes, int n_in,
                              void* d_out, int out_size) {
    const float* zf  = (const float*)d_in[0];
    const float* zx  = (const float*)d_in[1];
    const float* ze  = (const float*)d_in[2];
    const float* Wx1 = (const float*)d_in[3];
    const float* bx1 = (const float*)d_in[4];
    const float* Wx2 = (const float*)d_in[5];
    const float* bx2 = (const float*)d_in[6];
    const float* We1 = (const float*)d_in[7];
    const float* be1 = (const float*)d_in[8];
    const float* We2 = (const float*)d_in[9];
    const float* be2 = (const float*)d_in[10];
    const float* Wf1 = (const float*)d_in[11];
    const float* bf1 = (const float*)d_in[12];
    const float* Wf2 = (const float*)d_in[13];
    const float* bf2 = (const float*)d_in[14];
    const void*  dirs = d_in[15];
    float* out = (float*)d_out;

    // Per-launch reset of min/max encodings (graph-capturable memset nodes).
    void* pmin = nullptr; void* pmax = nullptr;
    cudaGetSymbolAddress(&pmin, g_minbits);
    cudaGetSymbolAddress(&pmax, g_maxbits);
    cudaMemsetAsync(pmin, 0xFF, C_CH * sizeof(unsigned int));  // 0xFFFFFFFF = +inf encoded
    cudaMemsetAsync(pmax, 0x00, C_CH * sizeof(unsigned int));  // 0x00000000 = -inf encoded

    pass_x_kernel<<<2049, 256>>>(zx, Wx1, bx1, Wx2, bx2,
                                 zf, Wf1, bf1, Wf2, bf2, dirs);
    pass_e_kernel<<<dim3(16, 128), 256>>>(ze, We1, be1, We2, be2);
    out_kernel<<<dim3(N_PTS / 128, C_CH / 32), dim3(32, 8)>>>(out);
}

// round 10
// speedup vs baseline: 1.0060x; 1.0060x over previous
#include <cuda_runtime.h>
#include <cuda_bf16.h>
#include <math.h>
#include <stdint.h>

#define C_CH   128
#define N_PTS  32768
#define K_PWL  20
#define LATENT 8
#define HID    8
#define NSEG   (K_PWL - 1)

// ---------------- scratch (static device memory; no allocations) ----------------
__device__ float g_x[(size_t)C_CH * N_PTS];     // raw x MLP outputs [C][N]
__device__ float g_e[(size_t)C_CH * N_PTS];     // raw e MLP outputs [C][N]
__device__ float g_slope[C_CH * NSEG];          // per-channel PWL segment slopes
__device__ float g_icept[C_CH * NSEG];          // per-channel PWL segment intercepts
__device__ unsigned int g_minbits[C_CH];
__device__ unsigned int g_maxbits[C_CH];
__device__ float g_minv[C_CH];
__device__ float g_scale[C_CH];
__device__ float g_psum[2048];
__device__ float g_psumsq[2048];
__device__ float g_eA;   // 0.1 * invstd
__device__ float g_eB;   // -0.1 * mean * invstd
__device__ unsigned int g_done;  // zero-init; reset by finalize each run

// MLP weights in constant memory -> LDCU/uniform-register operands, freeing ~81
// per-thread registers in the pass kernels (occupancy lever).
__constant__ float c_Wx1[64];
__constant__ float c_bx1[HID];
__constant__ float c_Wx2[HID];
__constant__ float c_bx2[1];
__constant__ float c_We1[64];
__constant__ float c_be1[HID];
__constant__ float c_We2[HID];
__constant__ float c_be2[1];

// xp = linspace(0,1,20) in f32
#define XPV(k) ((float)((double)(k) / 19.0))
__constant__ float c_xp[K_PWL] = {
    XPV(0), XPV(1), XPV(2), XPV(3), XPV(4), XPV(5), XPV(6), XPV(7), XPV(8), XPV(9),
    XPV(10), XPV(11), XPV(12), XPV(13), XPV(14), XPV(15), XPV(16), XPV(17), XPV(18), XPV(19)
};

// ---------------- helpers ----------------
__device__ __forceinline__ unsigned int fenc(float f) {
    unsigned int u = __float_as_uint(f);
    return (u >> 31) ? ~u : (u | 0x80000000u);
}
__device__ __forceinline__ float fdec(unsigned int u) {
    return (u & 0x80000000u) ? __uint_as_float(u & 0x7FFFFFFFu) : __uint_as_float(~u);
}

// Fast, tight-absolute-error tanh: (e^{2x}-1)/(e^{2x}+1). abs err ~1e-7.
__device__ __forceinline__ float tanh_fast(float x) {
    x = fminf(fmaxf(x, -30.0f), 30.0f);
    float t = __expf(2.0f * x);
    return __fdividef(t - 1.0f, t + 1.0f);
}

// ---------------- K1: PWL generator (tiny) + slope/intercept tables + init ----------------
__global__ void gen_pwl_kernel(const float* __restrict__ zf,
                               const float* __restrict__ Wf1, const float* __restrict__ bf1,
                               const float* __restrict__ Wf2, const float* __restrict__ bf2,
                               const void* __restrict__ dirs_raw) {
    int c = threadIdx.x;  // 128 threads, one per channel
    // Parallel dtype detection for `directions`:
    //   bit0 -> some byte at offset %4 != 0 is nonzero  (NOT int32 0/1)
    //   bit1 -> some byte value > 1                     (NOT a 0/1 byte array)
    __shared__ unsigned int flags;
    if (c == 0) { flags = 0u; g_done = 0u; }
    __syncthreads();
    {
        unsigned char v = ((const unsigned char*)dirs_raw)[c];
        unsigned int f = 0u;
        if ((c & 3) != 0 && v != 0) f |= 1u;
        if (v > 1) f |= 2u;
        if (f) atomicOr(&flags, f);
    }
    __syncthreads();
    // mode: 0 = int32, 1 = uint8/bool, 2 = float32
    const int mode = (!(flags & 1u)) ? 0 : ((!(flags & 2u)) ? 1 : 2);

    float z[LATENT];
#pragma unroll
    for (int i = 0; i < LATENT; i++) z[i] = zf[c * LATENT + i];

    float h[HID];
#pragma unroll
    for (int j = 0; j < HID; j++) h[j] = bf1[j];
#pragma unroll
    for (int i = 0; i < LATENT; i++)
#pragma unroll
        for (int j = 0; j < HID; j++) h[j] = fmaf(z[i], Wf1[i * HID + j], h[j]);
#pragma unroll
    for (int j = 0; j < HID; j++) h[j] = tanh_fast(h[j]);

    float pts[K_PWL];
#pragma unroll
    for (int k = 0; k < K_PWL; k++) {
        float s = bf2[k];
#pragma unroll
        for (int j = 0; j < HID; j++) s = fmaf(h[j], Wf2[j * K_PWL + k], s);
        pts[k] = tanh_fast(s);
    }
    // insertion sort ascending
    for (int a = 1; a < K_PWL; a++) {
        float v = pts[a];
        int b = a - 1;
        while (b >= 0 && pts[b] > v) { pts[b + 1] = pts[b]; b--; }
        pts[b + 1] = v;
    }
    bool dir;
    if (mode == 0)      dir = ((const int*)dirs_raw)[c] != 0;
    else if (mode == 1) dir = ((const unsigned char*)dirs_raw)[c] != 0;
    else                dir = ((const float*)dirs_raw)[c] > 0.5f;

    // Per-segment slope/intercept: y(xv) = sl*xv + ic on [xp[k], xp[k+1]]
    for (int k = 0; k < NSEG; k++) {
        float y0 = dir ? pts[k]     : pts[K_PWL - 1 - k];
        float y1 = dir ? pts[k + 1] : pts[K_PWL - 2 - k];
        float sl = (y1 - y0) / (c_xp[k + 1] - c_xp[k] + 1e-7f);
        g_slope[c * NSEG + k] = sl;
        g_icept[c * NSEG + k] = fmaf(-c_xp[k], sl, y0);
    }

    g_minbits[c] = 0xFFFFFFFFu;
    g_maxbits[c] = 0u;
}

// ---------------- K2: x MLP + per-channel min/max ----------------
__global__ void __launch_bounds__(256) pass_x_kernel(const float* __restrict__ zx) {
    const int c = blockIdx.y;
    const int tid = threadIdx.x;
    const size_t base = (size_t)c * N_PTS;
    const int n0 = blockIdx.x * 2048;

    float lmin = 1e30f, lmax = -1e30f;
#pragma unroll
    for (int k = 0; k < 8; k++) {
        int n = n0 + k * 256 + tid;
        const float4* p = reinterpret_cast<const float4*>(zx + (base + n) * LATENT);
        float4 a = p[0], bq = p[1];
        float z[8] = {a.x, a.y, a.z, a.w, bq.x, bq.y, bq.z, bq.w};
        float h[HID];
#pragma unroll
        for (int j = 0; j < HID; j++) h[j] = c_bx1[j];
#pragma unroll
        for (int i = 0; i < LATENT; i++)
#pragma unroll
            for (int j = 0; j < HID; j++) h[j] = fmaf(z[i], c_Wx1[i * HID + j], h[j]);
        float o = c_bx2[0];
#pragma unroll
        for (int j = 0; j < HID; j++) o = fmaf(tanh_fast(h[j]), c_Wx2[j], o);
        float xv = tanh_fast(o);
        g_x[base + n] = xv;
        lmin = fminf(lmin, xv);
        lmax = fmaxf(lmax, xv);
    }

    __shared__ float red[256];
    red[tid] = lmin; __syncthreads();
    for (int s = 128; s; s >>= 1) { if (tid < s) red[tid] = fminf(red[tid], red[tid + s]); __syncthreads(); }
    if (tid == 0) atomicMin(&g_minbits[c], fenc(red[0]));
    __syncthreads();
    red[tid] = lmax; __syncthreads();
    for (int s = 128; s; s >>= 1) { if (tid < s) red[tid] = fmaxf(red[tid], red[tid + s]); __syncthreads(); }
    if (tid == 0) atomicMax(&g_maxbits[c], fenc(red[0]));
}

// ---------------- K3: e MLP + global sum/sumsq partials + last-block finalize ----------------
__global__ void __launch_bounds__(256) pass_e_kernel(const float* __restrict__ ze) {
    const int c = blockIdx.y;
    const int tid = threadIdx.x;
    const size_t base = (size_t)c * N_PTS;
    const int n0 = blockIdx.x * 2048;

    float ls = 0.0f, lq = 0.0f;
#pragma unroll
    for (int k = 0; k < 8; k++) {
        int n = n0 + k * 256 + tid;
        const float4* p = reinterpret_cast<const float4*>(ze + (base + n) * LATENT);
        float4 a = p[0], bq = p[1];
        float z[8] = {a.x, a.y, a.z, a.w, bq.x, bq.y, bq.z, bq.w};
        float h[HID];
#pragma unroll
        for (int j = 0; j < HID; j++) h[j] = c_be1[j];
#pragma unroll
        for (int i = 0; i < LATENT; i++)
#pragma unroll
            for (int j = 0; j < HID; j++) h[j] = fmaf(z[i], c_We1[i * HID + j], h[j]);
        float o = c_be2[0];
#pragma unroll
        for (int j = 0; j < HID; j++) o = fmaf(tanh_fast(h[j]), c_We2[j], o);
        float ev = tanh_fast(o);
        g_e[base + n] = ev;
        ls += ev;
        lq = fmaf(ev, ev, lq);
    }

    __shared__ float reds[256];
    __shared__ float redq[256];
    __shared__ bool amLast;
    reds[tid] = ls; redq[tid] = lq; __syncthreads();
    for (int s = 128; s; s >>= 1) {
        if (tid < s) { reds[tid] += reds[tid + s]; redq[tid] += redq[tid + s]; }
        __syncthreads();
    }
    if (tid == 0) {
        int pid = blockIdx.y * gridDim.x + blockIdx.x;
        g_psum[pid] = reds[0];
        g_psumsq[pid] = redq[0];
        __threadfence();                       // release partials
        unsigned int t = atomicAdd(&g_done, 1u);
        amLast = (t == 2048u - 1u);
    }
    __syncthreads();

    // Last block performs the deterministic fixed-order fp64 reduce.
    if (amLast) {
        __threadfence();                       // acquire all partials
        __shared__ double sds[256];
        __shared__ double sdq[256];
        double s = 0.0, q = 0.0;
#pragma unroll
        for (int i = 0; i < 8; i++) {
            int idx = tid + i * 256;
            s += (double)g_psum[idx];
            q += (double)g_psumsq[idx];
        }
        sds[tid] = s; sdq[tid] = q; __syncthreads();
        for (int k = 128; k; k >>= 1) {
            if (tid < k) { sds[tid] += sds[tid + k]; sdq[tid] += sdq[tid + k]; }
            __syncthreads();
        }
        if (tid == 0) {
            double CN = (double)C_CH * (double)N_PTS;
            double mean = sds[0] / CN;
            double var = (sdq[0] - sds[0] * sds[0] / CN) / (CN - 1.0);
            double invstd = 1.0 / sqrt(var);
            g_eA = (float)(0.1 * invstd);
            g_eB = (float)(-0.1 * mean * invstd);
            g_done = 0u;                       // reset for next graph replay
        }
        if (tid < C_CH) {
            float mn = fdec(g_minbits[tid]);   // pass_x completed before this kernel (stream order)
            float mx = fdec(g_maxbits[tid]);
            g_minv[tid] = mn;
            g_scale[tid] = 1.0f / (mx - mn);
        }
        __threadfence();
    }
}

// ---------------- K4: transpose + direct-index PWL + noise ----------------
// Block covers 32 channels x 128 n (4 sub-tiles of 32x32).
__global__ void __launch_bounds__(256) out_kernel(float* __restrict__ out) {
    __shared__ float sx[32][33];
    __shared__ float se[32][33];
    __shared__ float ssl[32][NSEG + 1];
    __shared__ float ssb[32][NSEG + 1];
    __shared__ float smn[32];
    __shared__ float ssc[32];

    const int tx = threadIdx.x, ty = threadIdx.y;
    const int tid = ty * 32 + tx;
    const int nb = blockIdx.x * 128;
    const int c0 = blockIdx.y * 32;

    for (int idx = tid; idx < 32 * NSEG; idx += 256) {
        int cl = idx / NSEG, k = idx % NSEG;
        ssl[cl][k] = g_slope[(c0 + cl) * NSEG + k];
        ssb[cl][k] = g_icept[(c0 + cl) * NSEG + k];
    }
    if (tid < 32) {
        smn[tid] = g_minv[c0 + tid];
        ssc[tid] = g_scale[c0 + tid];
    }
    const float eA = g_eA, eB = g_eB;
    __syncthreads();

    const float mn = smn[tx], sc = ssc[tx];

#pragma unroll
    for (int t = 0; t < 4; t++) {
        const int n0 = nb + t * 32;
#pragma unroll
        for (int r = 0; r < 4; r++) {
            int cl = ty + r * 8;
            size_t off = (size_t)(c0 + cl) * N_PTS + n0 + tx;
            sx[cl][tx] = g_x[off];
            se[cl][tx] = g_e[off];
        }
        __syncthreads();
#pragma unroll
        for (int r = 0; r < 4; r++) {
            int nn = ty + r * 8;
            float xv = (sx[tx][nn] - mn) * sc;
            int j = min(max(__float2int_rd(xv * 19.0f), 0), NSEG - 1);
            float y = fmaf(xv, ssl[tx][j], ssb[tx][j]);
            out[(size_t)(n0 + nn) * C_CH + c0 + tx] = fmaf(se[tx][nn], eA, y + eB);
        }
        __syncthreads();
    }
}

// ---------------- launch ----------------
extern "C" void kernel_launch(void* const* d_in, const int* in_sizes, int n_in,
                              void* d_out, int out_size) {
    const float* zf  = (const float*)d_in[0];
    const float* zx  = (const float*)d_in[1];
    const float* ze  = (const float*)d_in[2];
    const float* Wx1 = (const float*)d_in[3];
    const float* bx1 = (const float*)d_in[4];
    const float* Wx2 = (const float*)d_in[5];
    const float* bx2 = (const float*)d_in[6];
    const float* We1 = (const float*)d_in[7];
    const float* be1 = (const float*)d_in[8];
    const float* We2 = (const float*)d_in[9];
    const float* be2 = (const float*)d_in[10];
    const float* Wf1 = (const float*)d_in[11];
    const float* bf1 = (const float*)d_in[12];
    const float* Wf2 = (const float*)d_in[13];
    const float* bf2 = (const float*)d_in[14];
    const void*  dirs = d_in[15];
    float* out = (float*)d_out;

    // Stage MLP weights into __constant__ (device->device async copies; capture-safe).
    void* p;
    cudaGetSymbolAddress(&p, c_Wx1); cudaMemcpyAsync(p, Wx1, 64 * 4, cudaMemcpyDeviceToDevice);
    cudaGetSymbolAddress(&p, c_bx1); cudaMemcpyAsync(p, bx1, HID * 4, cudaMemcpyDeviceToDevice);
    cudaGetSymbolAddress(&p, c_Wx2); cudaMemcpyAsync(p, Wx2, HID * 4, cudaMemcpyDeviceToDevice);
    cudaGetSymbolAddress(&p, c_bx2); cudaMemcpyAsync(p, bx2, 1 * 4, cudaMemcpyDeviceToDevice);
    cudaGetSymbolAddress(&p, c_We1); cudaMemcpyAsync(p, We1, 64 * 4, cudaMemcpyDeviceToDevice);
    cudaGetSymbolAddress(&p, c_be1); cudaMemcpyAsync(p, be1, HID * 4, cudaMemcpyDeviceToDevice);
    cudaGetSymbolAddress(&p, c_We2); cudaMemcpyAsync(p, We2, HID * 4, cudaMemcpyDeviceToDevice);
    cudaGetSymbolAddress(&p, c_be2); cudaMemcpyAsync(p, be2, 1 * 4, cudaMemcpyDeviceToDevice);

    gen_pwl_kernel<<<1, 128>>>(zf, Wf1, bf1, Wf2, bf2, dirs);
    pass_x_kernel<<<dim3(16, 128), 256>>>(zx);
    pass_e_kernel<<<dim3(16, 128), 256>>>(ze);
    out_kernel<<<dim3(N_PTS / 128, C_CH / 32), dim3(32, 8)>>>(out);
}

// round 11
// speedup vs baseline: 1.0810x; 1.0745x over previous
#include <cuda_runtime.h>
#include <cuda_bf16.h>
#include <math.h>
#include <stdint.h>

#define C_CH   128
#define N_PTS  32768
#define K_PWL  20
#define LATENT 8
#define HID    8
#define NSEG   (K_PWL - 1)

// ---------------- scratch (static device memory; no allocations) ----------------
__device__ float g_x[(size_t)C_CH * N_PTS];     // raw x MLP outputs [C][N]
__device__ float g_e[(size_t)C_CH * N_PTS];     // raw e MLP outputs [C][N]
__device__ float g_slope[C_CH * NSEG];          // per-channel PWL segment slopes
__device__ float g_icept[C_CH * NSEG];          // per-channel PWL segment intercepts
__device__ unsigned int g_minbits[C_CH];
__device__ unsigned int g_maxbits[C_CH];
__device__ float g_minv[C_CH];
__device__ float g_scale[C_CH];
__device__ float g_psum[2048];
__device__ float g_psumsq[2048];
__device__ float g_eA;   // 0.1 * invstd
__device__ float g_eB;   // -0.1 * mean * invstd
__device__ unsigned int g_done;  // zero-init; reset by finalize each run

// xp = linspace(0,1,20) in f32
#define XPV(k) ((float)((double)(k) / 19.0))
__constant__ float c_xp[K_PWL] = {
    XPV(0), XPV(1), XPV(2), XPV(3), XPV(4), XPV(5), XPV(6), XPV(7), XPV(8), XPV(9),
    XPV(10), XPV(11), XPV(12), XPV(13), XPV(14), XPV(15), XPV(16), XPV(17), XPV(18), XPV(19)
};

// ---------------- helpers ----------------
__device__ __forceinline__ unsigned int fenc(float f) {
    unsigned int u = __float_as_uint(f);
    return (u >> 31) ? ~u : (u | 0x80000000u);
}
__device__ __forceinline__ float fdec(unsigned int u) {
    return (u & 0x80000000u) ? __uint_as_float(u & 0x7FFFFFFFu) : __uint_as_float(~u);
}

// Fast, tight-absolute-error tanh: (e^{2x}-1)/(e^{2x}+1). abs err ~1e-7.
__device__ __forceinline__ float tanh_fast(float x) {
    x = fminf(fmaxf(x, -30.0f), 30.0f);
    float t = __expf(2.0f * x);
    return __fdividef(t - 1.0f, t + 1.0f);
}

// ---------------- shared-memory weight block for the pass kernels ----------------
// Layout (floats): [0:64) W1 row-major, [64:72) b1, [72:80) W2, [80] b2.
struct PassSmem {
    float w[84];        // 16B-aligned region for float4 LDS
    float red1[256];
    float red2[256];
};

__device__ __forceinline__ void load_weights_smem(
    float* sw, int tid,
    const float* __restrict__ W1, const float* __restrict__ b1,
    const float* __restrict__ W2, const float* __restrict__ b2) {
    if (tid < 64) sw[tid] = __ldg(W1 + tid);
    else if (tid < 72) sw[tid] = __ldg(b1 + tid - 64);
    else if (tid < 80) sw[tid] = __ldg(W2 + tid - 72);
    else if (tid == 80) sw[tid] = __ldg(b2);
    else if (tid < 84) sw[tid] = 0.0f;
}

// MLP for one point; weights read from smem (float4 LDS, broadcast).
__device__ __forceinline__ float mlp_point_smem(const float* sw, float4 a, float4 bq) {
    const float4* sw4 = reinterpret_cast<const float4*>(sw);
    float4 b1a = sw4[16], b1b = sw4[17];           // b1
    float h0 = b1a.x, h1 = b1a.y, h2 = b1a.z, h3 = b1a.w;
    float h4 = b1b.x, h5 = b1b.y, h6 = b1b.z, h7 = b1b.w;
    float z[8] = {a.x, a.y, a.z, a.w, bq.x, bq.y, bq.z, bq.w};
#pragma unroll
    for (int i = 0; i < 8; i++) {
        float zi = z[i];
        float4 wA = sw4[i * 2 + 0];
        float4 wB = sw4[i * 2 + 1];
        h0 = fmaf(zi, wA.x, h0); h1 = fmaf(zi, wA.y, h1);
        h2 = fmaf(zi, wA.z, h2); h3 = fmaf(zi, wA.w, h3);
        h4 = fmaf(zi, wB.x, h4); h5 = fmaf(zi, wB.y, h5);
        h6 = fmaf(zi, wB.z, h6); h7 = fmaf(zi, wB.w, h7);
    }
    float4 w2a = sw4[18], w2b = sw4[19];           // W2
    float o = sw[80];                              // b2
    o = fmaf(tanh_fast(h0), w2a.x, o);
    o = fmaf(tanh_fast(h1), w2a.y, o);
    o = fmaf(tanh_fast(h2), w2a.z, o);
    o = fmaf(tanh_fast(h3), w2a.w, o);
    o = fmaf(tanh_fast(h4), w2b.x, o);
    o = fmaf(tanh_fast(h5), w2b.y, o);
    o = fmaf(tanh_fast(h6), w2b.z, o);
    o = fmaf(tanh_fast(h7), w2b.w, o);
    return tanh_fast(o);
}

// ---------------- K1: PWL generator (tiny) + slope/intercept tables + init ----------------
__global__ void gen_pwl_kernel(const float* __restrict__ zf,
                               const float* __restrict__ Wf1, const float* __restrict__ bf1,
                               const float* __restrict__ Wf2, const float* __restrict__ bf2,
                               const void* __restrict__ dirs_raw) {
    int c = threadIdx.x;  // 128 threads, one per channel
    // Parallel dtype detection for `directions`:
    //   bit0 -> some byte at offset %4 != 0 is nonzero  (NOT int32 0/1)
    //   bit1 -> some byte value > 1                     (NOT a 0/1 byte array)
    __shared__ unsigned int flags;
    if (c == 0) { flags = 0u; g_done = 0u; }
    __syncthreads();
    {
        unsigned char v = ((const unsigned char*)dirs_raw)[c];
        unsigned int f = 0u;
        if ((c & 3) != 0 && v != 0) f |= 1u;
        if (v > 1) f |= 2u;
        if (f) atomicOr(&flags, f);
    }
    __syncthreads();
    // mode: 0 = int32, 1 = uint8/bool, 2 = float32
    const int mode = (!(flags & 1u)) ? 0 : ((!(flags & 2u)) ? 1 : 2);

    float z[LATENT];
#pragma unroll
    for (int i = 0; i < LATENT; i++) z[i] = zf[c * LATENT + i];

    float h[HID];
#pragma unroll
    for (int j = 0; j < HID; j++) h[j] = bf1[j];
#pragma unroll
    for (int i = 0; i < LATENT; i++)
#pragma unroll
        for (int j = 0; j < HID; j++) h[j] = fmaf(z[i], Wf1[i * HID + j], h[j]);
#pragma unroll
    for (int j = 0; j < HID; j++) h[j] = tanh_fast(h[j]);

    float pts[K_PWL];
#pragma unroll
    for (int k = 0; k < K_PWL; k++) {
        float s = bf2[k];
#pragma unroll
        for (int j = 0; j < HID; j++) s = fmaf(h[j], Wf2[j * K_PWL + k], s);
        pts[k] = tanh_fast(s);
    }
    // insertion sort ascending
    for (int a = 1; a < K_PWL; a++) {
        float v = pts[a];
        int b = a - 1;
        while (b >= 0 && pts[b] > v) { pts[b + 1] = pts[b]; b--; }
        pts[b + 1] = v;
    }
    bool dir;
    if (mode == 0)      dir = ((const int*)dirs_raw)[c] != 0;
    else if (mode == 1) dir = ((const unsigned char*)dirs_raw)[c] != 0;
    else                dir = ((const float*)dirs_raw)[c] > 0.5f;

    // Per-segment slope/intercept: y(xv) = sl*xv + ic on [xp[k], xp[k+1]]
    for (int k = 0; k < NSEG; k++) {
        float y0 = dir ? pts[k]     : pts[K_PWL - 1 - k];
        float y1 = dir ? pts[k + 1] : pts[K_PWL - 2 - k];
        float sl = (y1 - y0) / (c_xp[k + 1] - c_xp[k] + 1e-7f);
        g_slope[c * NSEG + k] = sl;
        g_icept[c * NSEG + k] = fmaf(-c_xp[k], sl, y0);
    }

    g_minbits[c] = 0xFFFFFFFFu;
    g_maxbits[c] = 0u;
}

// ---------------- K2: x MLP + per-channel min/max ----------------
// __launch_bounds__(256, 6): cap at ~40 regs -> 48 warps/SM. Weights live in
// smem; the reg cap prevents ptxas from hoisting them into per-thread regs.
__global__ void __launch_bounds__(256, 6) pass_x_kernel(
    const float* __restrict__ zx,
    const float* __restrict__ W1, const float* __restrict__ b1,
    const float* __restrict__ W2, const float* __restrict__ b2) {
    __shared__ PassSmem sm;
    const int tid = threadIdx.x;
    load_weights_smem(sm.w, tid, W1, b1, W2, b2);
    __syncthreads();

    const int c = blockIdx.y;
    const size_t base = (size_t)c * N_PTS;
    const int n0 = blockIdx.x * 2048;

    float lmin = 1e30f, lmax = -1e30f;
#pragma unroll
    for (int k = 0; k < 8; k++) {
        int n = n0 + k * 256 + tid;
        const float4* p = reinterpret_cast<const float4*>(zx + (base + n) * LATENT);
        float4 a = p[0], bq = p[1];
        float xv = mlp_point_smem(sm.w, a, bq);
        g_x[base + n] = xv;
        lmin = fminf(lmin, xv);
        lmax = fmaxf(lmax, xv);
    }

    sm.red1[tid] = lmin; sm.red2[tid] = lmax; __syncthreads();
    for (int s = 128; s; s >>= 1) {
        if (tid < s) {
            sm.red1[tid] = fminf(sm.red1[tid], sm.red1[tid + s]);
            sm.red2[tid] = fmaxf(sm.red2[tid], sm.red2[tid + s]);
        }
        __syncthreads();
    }
    if (tid == 0) {
        atomicMin(&g_minbits[c], fenc(sm.red1[0]));
        atomicMax(&g_maxbits[c], fenc(sm.red2[0]));
    }
}

// ---------------- K3: e MLP + global sum/sumsq partials + last-block finalize ----------------
__global__ void __launch_bounds__(256, 6) pass_e_kernel(
    const float* __restrict__ ze,
    const float* __restrict__ W1, const float* __restrict__ b1,
    const float* __restrict__ W2, const float* __restrict__ b2) {
    __shared__ PassSmem sm;
    const int tid = threadIdx.x;
    load_weights_smem(sm.w, tid, W1, b1, W2, b2);
    __syncthreads();

    const int c = blockIdx.y;
    const size_t base = (size_t)c * N_PTS;
    const int n0 = blockIdx.x * 2048;

    float ls = 0.0f, lq = 0.0f;
#pragma unroll
    for (int k = 0; k < 8; k++) {
        int n = n0 + k * 256 + tid;
        const float4* p = reinterpret_cast<const float4*>(ze + (base + n) * LATENT);
        float4 a = p[0], bq = p[1];
        float ev = mlp_point_smem(sm.w, a, bq);
        g_e[base + n] = ev;
        ls += ev;
        lq = fmaf(ev, ev, lq);
    }

    __shared__ bool amLast;
    sm.red1[tid] = ls; sm.red2[tid] = lq; __syncthreads();
    for (int s = 128; s; s >>= 1) {
        if (tid < s) { sm.red1[tid] += sm.red1[tid + s]; sm.red2[tid] += sm.red2[tid + s]; }
        __syncthreads();
    }
    if (tid == 0) {
        int pid = blockIdx.y * gridDim.x + blockIdx.x;
        g_psum[pid] = sm.red1[0];
        g_psumsq[pid] = sm.red2[0];
        __threadfence();                       // release partials
        unsigned int t = atomicAdd(&g_done, 1u);
        amLast = (t == 2048u - 1u);
    }
    __syncthreads();

    // Last block performs the deterministic fixed-order fp64 reduce.
    if (amLast) {
        __threadfence();                       // acquire all partials
        double s = 0.0, q = 0.0;
#pragma unroll
        for (int i = 0; i < 8; i++) {
            int idx = tid + i * 256;
            s += (double)g_psum[idx];
            q += (double)g_psumsq[idx];
        }
        // reuse red1/red2 as a double array (1KB+1KB = enough for 256 doubles)
        double* sds = reinterpret_cast<double*>(sm.red1);
        sds[tid] = s; __syncthreads();
        for (int k = 128; k; k >>= 1) {
            if (tid < k) sds[tid] += sds[tid + k];
            __syncthreads();
        }
        double stot = sds[0]; __syncthreads();
        sds[tid] = q; __syncthreads();
        for (int k = 128; k; k >>= 1) {
            if (tid < k) sds[tid] += sds[tid + k];
            __syncthreads();
        }
        double qtot = sds[0];
        if (tid == 0) {
            double CN = (double)C_CH * (double)N_PTS;
            double mean = stot / CN;
            double var = (qtot - stot * stot / CN) / (CN - 1.0);
            double invstd = 1.0 / sqrt(var);
            g_eA = (float)(0.1 * invstd);
            g_eB = (float)(-0.1 * mean * invstd);
            g_done = 0u;                       // reset for next graph replay
        }
        if (tid < C_CH) {
            float mn = fdec(g_minbits[tid]);   // pass_x completed before this kernel (stream order)
            float mx = fdec(g_maxbits[tid]);
            g_minv[tid] = mn;
            g_scale[tid] = 1.0f / (mx - mn);
        }
        __threadfence();
    }
}

// ---------------- K4: transpose + direct-index PWL + noise ----------------
// Block covers 32 channels x 128 n (4 sub-tiles of 32x32).
__global__ void __launch_bounds__(256) out_kernel(float* __restrict__ out) {
    __shared__ float sx[32][33];
    __shared__ float se[32][33];
    __shared__ float ssl[32][NSEG + 1];
    __shared__ float ssb[32][NSEG + 1];
    __shared__ float smn[32];
    __shared__ float ssc[32];

    const int tx = threadIdx.x, ty = threadIdx.y;
    const int tid = ty * 32 + tx;
    const int nb = blockIdx.x * 128;
    const int c0 = blockIdx.y * 32;

    for (int idx = tid; idx < 32 * NSEG; idx += 256) {
        int cl = idx / NSEG, k = idx % NSEG;
        ssl[cl][k] = g_slope[(c0 + cl) * NSEG + k];
        ssb[cl][k] = g_icept[(c0 + cl) * NSEG + k];
    }
    if (tid < 32) {
        smn[tid] = g_minv[c0 + tid];
        ssc[tid] = g_scale[c0 + tid];
    }
    const float eA = g_eA, eB = g_eB;
    __syncthreads();

    const float mn = smn[tx], sc = ssc[tx];

#pragma unroll
    for (int t = 0; t < 4; t++) {
        const int n0 = nb + t * 32;
#pragma unroll
        for (int r = 0; r < 4; r++) {
            int cl = ty + r * 8;
            size_t off = (size_t)(c0 + cl) * N_PTS + n0 + tx;
            sx[cl][tx] = g_x[off];
            se[cl][tx] = g_e[off];
        }
        __syncthreads();
#pragma unroll
        for (int r = 0; r < 4; r++) {
            int nn = ty + r * 8;
            float xv = (sx[tx][nn] - mn) * sc;
            int j = min(max(__float2int_rd(xv * 19.0f), 0), NSEG - 1);
            float y = fmaf(xv, ssl[tx][j], ssb[tx][j]);
            out[(size_t)(n0 + nn) * C_CH + c0 + tx] = fmaf(se[tx][nn], eA, y + eB);
        }
        __syncthreads();
    }
}

// ---------------- launch ----------------
extern "C" void kernel_launch(void* const* d_in, const int* in_sizes, int n_in,
                              void* d_out, int out_size) {
    const float* zf  = (const float*)d_in[0];
    const float* zx  = (const float*)d_in[1];
    const float* ze  = (const float*)d_in[2];
    const float* Wx1 = (const float*)d_in[3];
    const float* bx1 = (const float*)d_in[4];
    const float* Wx2 = (const float*)d_in[5];
    const float* bx2 = (const float*)d_in[6];
    const float* We1 = (const float*)d_in[7];
    const float* be1 = (const float*)d_in[8];
    const float* We2 = (const float*)d_in[9];
    const float* be2 = (const float*)d_in[10];
    const float* Wf1 = (const float*)d_in[11];
    const float* bf1 = (const float*)d_in[12];
    const float* Wf2 = (const float*)d_in[13];
    const float* bf2 = (const float*)d_in[14];
    const void*  dirs = d_in[15];
    float* out = (float*)d_out;

    gen_pwl_kernel<<<1, 128>>>(zf, Wf1, bf1, Wf2, bf2, dirs);
    pass_x_kernel<<<dim3(16, 128), 256>>>(zx, Wx1, bx1, Wx2, bx2);
    pass_e_kernel<<<dim3(16, 128), 256>>>(ze, We1, be1, We2, be2);
    out_kernel<<<dim3(N_PTS / 128, C_CH / 32), dim3(32, 8)>>>(out);
}